// round 5
// baseline (speedup 1.0000x reference)
#include <cuda_runtime.h>
#include <math.h>

#define BDIM 16
#define CO   64
#define RN   32            // Chebyshev nodes
#define CC   72            // padded channels: [0..63]=co, [64]=density, [65..71]=pad
#define RDIM 128

// ---------------- device globals (scratch) ----------------
__device__ unsigned g_lo_u, g_hi_u;
__device__ int g_cnt[BDIM + 1];                          // [0..15]: per-b stageA counters, [16]: prep
__device__ __align__(16) float g_s[RN];
__device__ __align__(16) float g_w[RN];
__device__ float g_a;
__device__ __align__(16) float g_K[RN * RN];
__device__ __align__(16) float g_A[BDIM * RN * CC];      // 147 KB, atomically accumulated
__device__ __align__(16) float g_Btd[BDIM * RN];
__device__ __align__(16) float g_WB[BDIM * RN * RDIM];   // 262 KB

__device__ __forceinline__ unsigned f2ord(float f) {
    unsigned u = __float_as_uint(f);
    return (u & 0x80000000u) ? ~u : (u | 0x80000000u);
}
__device__ __forceinline__ float ord2f(unsigned u) {
    return (u & 0x80000000u) ? __uint_as_float(u ^ 0x80000000u) : __uint_as_float(~u);
}

// ---------------- kernel 1: fused minmax + node setup (last-block tail) ----------------
__global__ void k_prep(const float* __restrict__ ci, const float* __restrict__ ti,
                       int nci, int nti, const float* __restrict__ ls) {
    __shared__ float ss[RN];
    __shared__ int last;
    int tid = threadIdx.x;

    // phase 1: partial min/max
    int total = nci + nti;
    float lo = 3.4e38f, hi = -3.4e38f;
    for (int i = blockIdx.x * blockDim.x + tid; i < total; i += gridDim.x * blockDim.x) {
        float v = (i < nci) ? ci[i] : ti[i - nci];
        lo = fminf(lo, v);
        hi = fmaxf(hi, v);
    }
    #pragma unroll
    for (int o = 16; o; o >>= 1) {
        lo = fminf(lo, __shfl_xor_sync(0xFFFFFFFFu, lo, o));
        hi = fmaxf(hi, __shfl_xor_sync(0xFFFFFFFFu, hi, o));
    }
    if ((tid & 31) == 0) {
        atomicMin(&g_lo_u, f2ord(lo));
        atomicMax(&g_hi_u, f2ord(hi));
    }
    __threadfence();
    __syncthreads();
    if (tid == 0)
        last = (atomicAdd(&g_cnt[BDIM], 1) == (int)gridDim.x - 1);
    __syncthreads();
    if (!last) return;

    // phase 2 (one block): nodes, weights, node-pair kernel matrix
    if (tid == 0) {
        float l = ls[0];
        g_a = -0.5f / (l * l);
    }
    if (tid < RN) {
        float flo = ord2f(atomicOr(&g_lo_u, 0u));
        float fhi = ord2f(atomicOr(&g_hi_u, 0u));
        float c = 0.5f * (flo + fhi);
        float h = 0.5f * (fhi - flo) * 1.0002f + 1e-5f;
        double ang = (double)tid * M_PI / (double)(RN - 1);
        float s = c + h * (float)cos(ang);
        g_s[tid] = s;
        ss[tid] = s;
        float wj = ((tid == 0) || (tid == RN - 1)) ? 0.5f : 1.0f;
        g_w[tid] = (tid & 1) ? -wj : wj;
    }
    __syncthreads();
    for (int i = tid; i < RN * RN; i += blockDim.x) {
        float d = ss[i >> 5] - ss[i & 31];
        g_K[i] = expf(g_a * d * d);
    }
}

// ---------------- kernel 2: stage A (+ fused stage B tail per batch) ----------------
// block 288 = 9 groups x 32 q
#define SA_LT    0                          // Lt[32][129]
#define SA_CO    (RN * 129)                 // 4128
#define SA_INVD  (SA_CO + 128 * CC)         // +9216 = 13344
#define SA_S     (SA_INVD + 128)
#define SA_W     (SA_S + RN)
#define SA_END   (SA_W + RN)                // 13504
// stage-B tail overlay (reuses [0, ...))
#define SB_AS    0                          // As[32][72]  = 2304
#define SB_KS    2304                       // Ks[32][32]  = 1024
#define SB_BT    3328                       // Bt[32][72]  = 2304
#define SB_WS    5632                       // Ws[128][65] = 8320 -> 13952
#define SA_FLOATS 13952                     // 55808 B

__global__ void __launch_bounds__(288)
k_stageA(const float* __restrict__ ci, const float* __restrict__ co,
         const float* __restrict__ W) {
    extern __shared__ float sm[];
    float* Lt   = sm + SA_LT;
    float* co_s = sm + SA_CO;
    float* invd = sm + SA_INVD;
    float* s_s  = sm + SA_S;
    float* w_s  = sm + SA_W;

    const int tid = threadIdx.x;
    const int chunk = blockIdx.x, b = blockIdx.y;
    const int n0 = chunk * 256;

    if (tid < RN) { s_s[tid] = g_s[tid]; w_s[tid] = g_w[tid]; }
    __syncthreads();

    const int q = tid & 31, g = tid >> 5;   // g 0..8
    float4 acc0 = make_float4(0.f, 0.f, 0.f, 0.f);
    float4 acc1 = make_float4(0.f, 0.f, 0.f, 0.f);

    for (int sub = 0; sub < 2; ++sub) {
        const int nb = n0 + sub * 128;
        __syncthreads();
        if (tid < 128) {
            float x = ci[(nb + tid) * BDIM + b];
            float den = 0.0f;
            #pragma unroll 8
            for (int j = 0; j < RN; ++j) {
                float d = x - s_s[j];
                if (d == 0.0f) d = 1e-30f;
                float r = __fdividef(w_s[j], d);
                den += r;
                Lt[j * 129 + tid] = r;
            }
            invd[tid] = __fdividef(1.0f, den);
        } else {
            for (int i = tid - 128; i < 128 * 18; i += 160) {
                int nn = i / 18, c4 = i - nn * 18;
                float4 v;
                if (c4 < 16)
                    v = ((const float4*)(co + ((size_t)(nb + nn) * BDIM + b) * CO))[c4];
                else if (c4 == 16)
                    v = make_float4(1.f, 0.f, 0.f, 0.f);
                else
                    v = make_float4(0.f, 0.f, 0.f, 0.f);
                ((float4*)co_s)[nn * 18 + c4] = v;
            }
        }
        __syncthreads();

        const float4* co4 = (const float4*)co_s;
        #pragma unroll 4
        for (int n = 0; n < 128; ++n) {
            float k = Lt[q * 129 + n] * invd[n];
            float4 x0 = co4[n * 18 + g * 2];
            float4 x1 = co4[n * 18 + g * 2 + 1];
            acc0.x = fmaf(k, x0.x, acc0.x); acc0.y = fmaf(k, x0.y, acc0.y);
            acc0.z = fmaf(k, x0.z, acc0.z); acc0.w = fmaf(k, x0.w, acc0.w);
            acc1.x = fmaf(k, x1.x, acc1.x); acc1.y = fmaf(k, x1.y, acc1.y);
            acc1.z = fmaf(k, x1.z, acc1.z); acc1.w = fmaf(k, x1.w, acc1.w);
        }
    }
    float* ap = g_A + ((size_t)b * RN + q) * CC + g * 8;
    atomicAdd(ap + 0, acc0.x); atomicAdd(ap + 1, acc0.y);
    atomicAdd(ap + 2, acc0.z); atomicAdd(ap + 3, acc0.w);
    atomicAdd(ap + 4, acc1.x); atomicAdd(ap + 5, acc1.y);
    atomicAdd(ap + 6, acc1.z); atomicAdd(ap + 7, acc1.w);

    // ---- fused stage B: last chunk-block for this b ----
    __threadfence();
    __shared__ int lastb;
    __syncthreads();   // smem reuse barrier + counter election below
    if (tid == 0)
        lastb = (atomicAdd(&g_cnt[b], 1) == (int)gridDim.x - 1);
    __syncthreads();
    if (!lastb) return;

    float* As = sm + SB_AS;
    float* Ks = sm + SB_KS;
    float* Bt = sm + SB_BT;
    float* Ws = sm + SB_WS;

    // L2-coherent reads of atomically-accumulated A
    for (int i = tid; i < RN * CC / 4; i += 288)
        ((float4*)As)[i] = __ldcg((const float4*)(g_A + (size_t)b * RN * CC) + i);
    for (int i = tid; i < RN * RN; i += 288) Ks[i] = g_K[i];
    for (int i = tid; i < RDIM * 65; i += 288) Ws[i] = W[i];
    __syncthreads();

    // Bt[p][c] = sum_q K[p][q] * As[q][c]
    for (int i = tid; i < RN * CC; i += 288) {
        int p = i / CC, c = i - p * CC;
        float acc = 0.0f;
        #pragma unroll 8
        for (int qq = 0; qq < RN; ++qq)
            acc = fmaf(Ks[p * RN + qq], As[qq * CC + c], acc);
        Bt[i] = acc;
        if (c == 64) g_Btd[b * RN + p] = acc;
    }
    __syncthreads();

    // WB[p][r] = sum_c Ws[r][c+1] * Bt[p][c]
    for (int i = tid; i < RN * RDIM; i += 288) {
        int r = i & 127, p = i >> 7;
        float acc = 0.0f;
        #pragma unroll 8
        for (int c = 0; c < 64; ++c)
            acc = fmaf(Ws[r * 65 + (c + 1)], Bt[p * CC + c], acc);
        g_WB[((size_t)b * RN + p) * RDIM + r] = acc;
    }
}

// ---------------- kernel 3: stage C  out = (L^T WB)/dens + W0*dens + bias ----------------
#define SC_LAT  0                           // Lat[32][132] = 4224
#define SC_WBS  (RN * 132)
#define SC_DENS (SC_WBS + RN * RDIM)        // +4096 = 8320
#define SC_BTD  (SC_DENS + 128)
#define SC_S    (SC_BTD + RN)
#define SC_W    (SC_S + RN)
#define SC_W0   (SC_W + RN)
#define SC_BIAS (SC_W0 + 128)
#define SC_FLOATS (SC_BIAS + 128)           // 8800 floats = 35200 B

__global__ void __launch_bounds__(256, 2)
k_stageC(const float* __restrict__ ti, const float* __restrict__ W,
         const float* __restrict__ bias, float* __restrict__ out) {
    extern __shared__ float sm[];
    float* Lat  = sm + SC_LAT;
    float* WBs  = sm + SC_WBS;
    float* dens = sm + SC_DENS;
    float* Btd  = sm + SC_BTD;
    float* s_s  = sm + SC_S;
    float* w_s  = sm + SC_W;
    float* W0s  = sm + SC_W0;
    float* bi_s = sm + SC_BIAS;

    const int tid = threadIdx.x;
    const int m0 = blockIdx.x * 128, b = blockIdx.y;

    for (int i = tid; i < RN * RDIM / 4; i += 256)
        ((float4*)WBs)[i] = ((const float4*)(g_WB + (size_t)b * RN * RDIM))[i];
    if (tid < RN) {
        Btd[tid] = g_Btd[b * RN + tid];
        s_s[tid] = g_s[tid];
        w_s[tid] = g_w[tid];
    }
    if (tid < 128) {
        W0s[tid]  = W[tid * 65];
        bi_s[tid] = bias[tid];
    }
    __syncthreads();

    if (tid < 128) {
        float x = ti[(m0 + tid) * BDIM + b];
        float den = 0.0f;
        #pragma unroll 8
        for (int j = 0; j < RN; ++j) {
            float d = x - s_s[j];
            if (d == 0.0f) d = 1e-30f;
            float r = __fdividef(w_s[j], d);
            den += r;
            Lat[j * 132 + tid] = r;
        }
        float inv = __fdividef(1.0f, den);
        float dm = 0.0f;
        #pragma unroll 8
        for (int j = 0; j < RN; ++j) {
            float v = Lat[j * 132 + tid] * inv;
            Lat[j * 132 + tid] = v;
            dm = fmaf(v, Btd[j], dm);
        }
        dens[tid] = dm;
    }
    __syncthreads();

    const int tx = tid & 15, ty = tid >> 4;
    const int mi = tx * 8, ri = ty * 8;
    float acc[8][8];
    #pragma unroll
    for (int k = 0; k < 8; ++k)
        #pragma unroll
        for (int j = 0; j < 8; ++j) acc[k][j] = 0.0f;

    const float4* Lat4 = (const float4*)Lat;
    const float4* WBs4 = (const float4*)WBs;
    #pragma unroll 4
    for (int p = 0; p < RN; ++p) {
        float4 a0 = Lat4[p * 33 + tx * 2];
        float4 a1 = Lat4[p * 33 + tx * 2 + 1];
        float4 b0 = WBs4[p * 32 + ty * 2];
        float4 b1 = WBs4[p * 32 + ty * 2 + 1];
        float am[8] = {a0.x, a0.y, a0.z, a0.w, a1.x, a1.y, a1.z, a1.w};
        float br[8] = {b0.x, b0.y, b0.z, b0.w, b1.x, b1.y, b1.z, b1.w};
        #pragma unroll
        for (int k = 0; k < 8; ++k)
            #pragma unroll
            for (int j = 0; j < 8; ++j)
                acc[k][j] = fmaf(am[k], br[j], acc[k][j]);
    }

    float w0[8], bi[8];
    #pragma unroll
    for (int j = 0; j < 8; ++j) { w0[j] = W0s[ri + j]; bi[j] = bi_s[ri + j]; }
    #pragma unroll
    for (int k = 0; k < 8; ++k) {
        float dm = dens[mi + k];
        float inv = __fdividef(1.0f, dm + 1e-8f);
        float o[8];
        #pragma unroll
        for (int j = 0; j < 8; ++j)
            o[j] = fmaf(acc[k][j], inv, fmaf(w0[j], dm, bi[j]));
        float* op = out + ((size_t)(m0 + mi + k) * BDIM + b) * RDIM + ri;
        ((float4*)op)[0] = make_float4(o[0], o[1], o[2], o[3]);
        ((float4*)op)[1] = make_float4(o[4], o[5], o[6], o[7]);
    }
}

// ---------------- launch ----------------
extern "C" void kernel_launch(void* const* d_in, const int* in_sizes, int n_in,
                              void* d_out, int out_size)
{
    const float* ci   = (const float*)d_in[0];
    const float* co   = (const float*)d_in[1];
    const float* ti   = (const float*)d_in[2];
    const float* ls   = (const float*)d_in[3];
    const float* W    = (const float*)d_in[4];
    const float* bias = (const float*)d_in[5];
    float* out = (float*)d_out;

    const int N = in_sizes[0] / BDIM;   // 2048
    const int M = in_sizes[2] / BDIM;   // 4096

    cudaFuncSetAttribute(k_stageA, cudaFuncAttributeMaxDynamicSharedMemorySize,
                         SA_FLOATS * 4);
    cudaFuncSetAttribute(k_stageC, cudaFuncAttributeMaxDynamicSharedMemorySize,
                         SC_FLOATS * 4);

    void *p_lo, *p_hi, *p_A, *p_cnt;
    cudaGetSymbolAddress(&p_lo,  g_lo_u);
    cudaGetSymbolAddress(&p_hi,  g_hi_u);
    cudaGetSymbolAddress(&p_A,   g_A);
    cudaGetSymbolAddress(&p_cnt, g_cnt);
    cudaMemsetAsync(p_lo,  0xFF, 4);
    cudaMemsetAsync(p_hi,  0x00, 4);
    cudaMemsetAsync(p_cnt, 0x00, (BDIM + 1) * sizeof(int));
    cudaMemsetAsync(p_A,   0x00, BDIM * RN * CC * sizeof(float));

    k_prep<<<96, 256>>>(ci, ti, N * BDIM, M * BDIM, ls);
    k_stageA<<<dim3(N / 256, BDIM), 288, SA_FLOATS * 4>>>(ci, co, W);
    k_stageC<<<dim3(M / 128, BDIM), 256, SC_FLOATS * 4>>>(ti, W, bias, out);
}

// round 6
// speedup vs baseline: 1.2145x; 1.2145x over previous
#include <cuda_runtime.h>
#include <math.h>

#define BDIM 16
#define CO   64
#define RN   24            // Chebyshev nodes
#define CC   72            // padded channels: [0..63]=co, [64]=density, [65..71]=pad
#define RDIM 128

// ---------------- device globals (scratch) ----------------
__device__ unsigned g_lo_u, g_hi_u;
__device__ __align__(16) float g_s[RN];
__device__ __align__(16) float g_w[RN];
__device__ float g_a;
__device__ __align__(16) float g_K[RN * RN];
__device__ __align__(16) float g_A[BDIM * RN * CC];      // atomically accumulated
__device__ __align__(16) float g_Btd[BDIM * RN];
__device__ __align__(16) float g_WB[BDIM * RN * RDIM];

__device__ __forceinline__ unsigned f2ord(float f) {
    unsigned u = __float_as_uint(f);
    return (u & 0x80000000u) ? ~u : (u | 0x80000000u);
}
__device__ __forceinline__ float ord2f(unsigned u) {
    return (u & 0x80000000u) ? __uint_as_float(u ^ 0x80000000u) : __uint_as_float(~u);
}

// ---------------- kernel 1: min/max over ci and ti ----------------
__global__ void k_minmax(const float* __restrict__ ci, const float* __restrict__ ti,
                         int nci, int nti) {
    int total = nci + nti;
    float lo = 3.4e38f, hi = -3.4e38f;
    for (int i = blockIdx.x * blockDim.x + threadIdx.x; i < total;
         i += gridDim.x * blockDim.x) {
        float v = (i < nci) ? ci[i] : ti[i - nci];
        lo = fminf(lo, v);
        hi = fmaxf(hi, v);
    }
    #pragma unroll
    for (int o = 16; o; o >>= 1) {
        lo = fminf(lo, __shfl_xor_sync(0xFFFFFFFFu, lo, o));
        hi = fmaxf(hi, __shfl_xor_sync(0xFFFFFFFFu, hi, o));
    }
    if ((threadIdx.x & 31) == 0) {
        atomicMin(&g_lo_u, f2ord(lo));
        atomicMax(&g_hi_u, f2ord(hi));
    }
}

// ---------------- kernel 2: nodes + weights + node-pair kernel matrix ----------------
__global__ void k_setup(const float* __restrict__ ls) {
    __shared__ float ss[RN];
    int tid = threadIdx.x;
    if (tid == 0) {
        float l = ls[0];
        g_a = -0.5f / (l * l);
    }
    if (tid < RN) {
        float lo = ord2f(g_lo_u), hi = ord2f(g_hi_u);
        float c = 0.5f * (lo + hi);
        float h = 0.5f * (hi - lo) * 1.0002f + 1e-5f;
        double ang = (double)tid * M_PI / (double)(RN - 1);
        float s = c + h * (float)cos(ang);
        g_s[tid] = s;
        ss[tid] = s;
        float wj = ((tid == 0) || (tid == RN - 1)) ? 0.5f : 1.0f;
        g_w[tid] = (tid & 1) ? -wj : wj;
    }
    __syncthreads();
    for (int i = tid; i < RN * RN; i += blockDim.x) {
        int p = i / RN, q = i - p * RN;
        float d = ss[p] - ss[q];
        g_K[i] = expf(g_a * d * d);
    }
}

// ---------------- kernel 3: stage A  g_A[b,q,cc] += sum_n L_q(ci_n)*co (atomic) ----------------
#define SA_LT    0                          // Lt[24][129] = 3096
#define SA_CO    3096                       // co_s[128][72] = 9216
#define SA_INVD  12312                      // invd[128]
#define SA_S     12440
#define SA_W     (SA_S + RN)
#define SA_FLOATS (SA_W + RN)               // 12488 floats = 49952 B

__global__ void __launch_bounds__(256)
k_stageA(const float* __restrict__ ci, const float* __restrict__ co) {
    extern __shared__ float sm[];
    float* Lt   = sm + SA_LT;
    float* co_s = sm + SA_CO;
    float* invd = sm + SA_INVD;
    float* s_s  = sm + SA_S;
    float* w_s  = sm + SA_W;

    const int tid = threadIdx.x;
    const int chunk = blockIdx.x, b = blockIdx.y;
    const int n0 = chunk * 256;

    if (tid < RN) { s_s[tid] = g_s[tid]; w_s[tid] = g_w[tid]; }
    __syncthreads();

    const int g = tid / 24, q = tid - g * 24;   // active when tid < 216: g 0..8, q 0..23
    const bool act = (tid < 216);
    float4 acc0 = make_float4(0.f, 0.f, 0.f, 0.f);
    float4 acc1 = make_float4(0.f, 0.f, 0.f, 0.f);

    for (int sub = 0; sub < 2; ++sub) {
        const int nb = n0 + sub * 128;
        __syncthreads();
        if (tid < 128) {
            float x = ci[(nb + tid) * BDIM + b];
            float den = 0.0f;
            #pragma unroll 8
            for (int j = 0; j < RN; ++j) {
                float d = x - s_s[j];
                if (d == 0.0f) d = 1e-30f;
                float r = __fdividef(w_s[j], d);
                den += r;
                Lt[j * 129 + tid] = r;
            }
            invd[tid] = __fdividef(1.0f, den);
        } else {
            for (int i = tid - 128; i < 128 * 18; i += 128) {
                int nn = i / 18, c4 = i - nn * 18;
                float4 v;
                if (c4 < 16)
                    v = ((const float4*)(co + ((size_t)(nb + nn) * BDIM + b) * CO))[c4];
                else if (c4 == 16)
                    v = make_float4(1.f, 0.f, 0.f, 0.f);
                else
                    v = make_float4(0.f, 0.f, 0.f, 0.f);
                ((float4*)co_s)[nn * 18 + c4] = v;
            }
        }
        __syncthreads();

        if (act) {
            const float4* co4 = (const float4*)co_s;
            #pragma unroll 4
            for (int n = 0; n < 128; ++n) {
                float k = Lt[q * 129 + n] * invd[n];
                float4 x0 = co4[n * 18 + g * 2];
                float4 x1 = co4[n * 18 + g * 2 + 1];
                acc0.x = fmaf(k, x0.x, acc0.x); acc0.y = fmaf(k, x0.y, acc0.y);
                acc0.z = fmaf(k, x0.z, acc0.z); acc0.w = fmaf(k, x0.w, acc0.w);
                acc1.x = fmaf(k, x1.x, acc1.x); acc1.y = fmaf(k, x1.y, acc1.y);
                acc1.z = fmaf(k, x1.z, acc1.z); acc1.w = fmaf(k, x1.w, acc1.w);
            }
        }
    }
    if (act) {
        float* ap = g_A + ((size_t)b * RN + q) * CC + g * 8;
        atomicAdd(ap + 0, acc0.x); atomicAdd(ap + 1, acc0.y);
        atomicAdd(ap + 2, acc0.z); atomicAdd(ap + 3, acc0.w);
        atomicAdd(ap + 4, acc1.x); atomicAdd(ap + 5, acc1.y);
        atomicAdd(ap + 6, acc1.z); atomicAdd(ap + 7, acc1.w);
    }
}

// ---------------- kernel 4: stage B  per (b, 16-r chunk): Bt = K*A ; WB slice = Bt*W^T ----------------
__global__ void __launch_bounds__(128)
k_stageB(const float* __restrict__ W) {
    __shared__ float As[RN * CC];            // 1728
    __shared__ float Ks[RN * RN];            // 576
    __shared__ float Bt[RN * CC];            // 1728
    __shared__ float Ws[16 * 65];            // 1040
    const int tid = threadIdx.x, b = blockIdx.x, rc = blockIdx.y;
    const int r0 = rc * 16;

    for (int i = tid; i < RN * CC / 4; i += 128)
        ((float4*)As)[i] = ((const float4*)(g_A + (size_t)b * RN * CC))[i];
    for (int i = tid; i < RN * RN; i += 128) Ks[i] = g_K[i];
    for (int i = tid; i < 16 * 65; i += 128) Ws[i] = W[r0 * 65 + i];
    __syncthreads();

    // Bt[p][c] = sum_q K[p][q] * As[q][c]
    for (int i = tid; i < RN * CC; i += 128) {
        int p = i / CC, c = i - p * CC;
        float acc = 0.0f;
        #pragma unroll 8
        for (int qq = 0; qq < RN; ++qq)
            acc = fmaf(Ks[p * RN + qq], As[qq * CC + c], acc);
        Bt[i] = acc;
        if (c == 64 && rc == 0) g_Btd[b * RN + p] = acc;
    }
    __syncthreads();

    // WB[p][r0+rr] = sum_c Ws[rr][c+1] * Bt[p][c]   (24*16 = 384 outputs)
    for (int i = tid; i < RN * 16; i += 128) {
        int p = i >> 4, rr = i & 15;
        float acc = 0.0f;
        #pragma unroll 8
        for (int c = 0; c < 64; ++c)
            acc = fmaf(Ws[rr * 65 + (c + 1)], Bt[p * CC + c], acc);
        g_WB[((size_t)b * RN + p) * RDIM + r0 + rr] = acc;
    }
}

// ---------------- kernel 5: stage C  out = (L^T WB)/dens + W0*dens + bias ----------------
#define SC_LAT  0                           // Lat[24][132] = 3168
#define SC_WBS  3168                        // WBs[24][128] = 3072
#define SC_DENS 6240                        // 128
#define SC_BTD  6368
#define SC_S    (SC_BTD + RN)
#define SC_W    (SC_S + RN)
#define SC_W0   (SC_W + RN)
#define SC_BIAS (SC_W0 + 128)
#define SC_FLOATS (SC_BIAS + 128)           // 6696 floats = 26784 B

__global__ void __launch_bounds__(256, 2)
k_stageC(const float* __restrict__ ti, const float* __restrict__ W,
         const float* __restrict__ bias, float* __restrict__ out) {
    extern __shared__ float sm[];
    float* Lat  = sm + SC_LAT;
    float* WBs  = sm + SC_WBS;
    float* dens = sm + SC_DENS;
    float* Btd  = sm + SC_BTD;
    float* s_s  = sm + SC_S;
    float* w_s  = sm + SC_W;
    float* W0s  = sm + SC_W0;
    float* bi_s = sm + SC_BIAS;

    const int tid = threadIdx.x;
    const int m0 = blockIdx.x * 128, b = blockIdx.y;

    for (int i = tid; i < RN * RDIM / 4; i += 256)
        ((float4*)WBs)[i] = ((const float4*)(g_WB + (size_t)b * RN * RDIM))[i];
    if (tid < RN) {
        Btd[tid] = g_Btd[b * RN + tid];
        s_s[tid] = g_s[tid];
        w_s[tid] = g_w[tid];
    }
    if (tid < 128) {
        W0s[tid]  = W[tid * 65];
        bi_s[tid] = bias[tid];
    }
    __syncthreads();

    if (tid < 128) {
        float x = ti[(m0 + tid) * BDIM + b];
        float den = 0.0f;
        #pragma unroll 8
        for (int j = 0; j < RN; ++j) {
            float d = x - s_s[j];
            if (d == 0.0f) d = 1e-30f;
            float r = __fdividef(w_s[j], d);
            den += r;
            Lat[j * 132 + tid] = r;
        }
        float inv = __fdividef(1.0f, den);
        float dm = 0.0f;
        #pragma unroll 8
        for (int j = 0; j < RN; ++j) {
            float v = Lat[j * 132 + tid] * inv;
            Lat[j * 132 + tid] = v;
            dm = fmaf(v, Btd[j], dm);
        }
        dens[tid] = dm;
    }
    __syncthreads();

    const int tx = tid & 15, ty = tid >> 4;
    const int mi = tx * 8, ri = ty * 8;
    float acc[8][8];
    #pragma unroll
    for (int k = 0; k < 8; ++k)
        #pragma unroll
        for (int j = 0; j < 8; ++j) acc[k][j] = 0.0f;

    const float4* Lat4 = (const float4*)Lat;
    const float4* WBs4 = (const float4*)WBs;
    #pragma unroll 4
    for (int p = 0; p < RN; ++p) {
        float4 a0 = Lat4[p * 33 + tx * 2];
        float4 a1 = Lat4[p * 33 + tx * 2 + 1];
        float4 b0 = WBs4[p * 32 + ty * 2];
        float4 b1 = WBs4[p * 32 + ty * 2 + 1];
        float am[8] = {a0.x, a0.y, a0.z, a0.w, a1.x, a1.y, a1.z, a1.w};
        float br[8] = {b0.x, b0.y, b0.z, b0.w, b1.x, b1.y, b1.z, b1.w};
        #pragma unroll
        for (int k = 0; k < 8; ++k)
            #pragma unroll
            for (int j = 0; j < 8; ++j)
                acc[k][j] = fmaf(am[k], br[j], acc[k][j]);
    }

    float w0[8], bi[8];
    #pragma unroll
    for (int j = 0; j < 8; ++j) { w0[j] = W0s[ri + j]; bi[j] = bi_s[ri + j]; }
    #pragma unroll
    for (int k = 0; k < 8; ++k) {
        float dm = dens[mi + k];
        float inv = __fdividef(1.0f, dm + 1e-8f);
        float o[8];
        #pragma unroll
        for (int j = 0; j < 8; ++j)
            o[j] = fmaf(acc[k][j], inv, fmaf(w0[j], dm, bi[j]));
        float* op = out + ((size_t)(m0 + mi + k) * BDIM + b) * RDIM + ri;
        ((float4*)op)[0] = make_float4(o[0], o[1], o[2], o[3]);
        ((float4*)op)[1] = make_float4(o[4], o[5], o[6], o[7]);
    }
}

// ---------------- launch ----------------
extern "C" void kernel_launch(void* const* d_in, const int* in_sizes, int n_in,
                              void* d_out, int out_size)
{
    const float* ci   = (const float*)d_in[0];
    const float* co   = (const float*)d_in[1];
    const float* ti   = (const float*)d_in[2];
    const float* ls   = (const float*)d_in[3];
    const float* W    = (const float*)d_in[4];
    const float* bias = (const float*)d_in[5];
    float* out = (float*)d_out;

    const int N = in_sizes[0] / BDIM;   // 2048
    const int M = in_sizes[2] / BDIM;   // 4096

    cudaFuncSetAttribute(k_stageA, cudaFuncAttributeMaxDynamicSharedMemorySize,
                         SA_FLOATS * 4);
    cudaFuncSetAttribute(k_stageC, cudaFuncAttributeMaxDynamicSharedMemorySize,
                         SC_FLOATS * 4);

    void *p_lo, *p_hi, *p_A;
    cudaGetSymbolAddress(&p_lo, g_lo_u);
    cudaGetSymbolAddress(&p_hi, g_hi_u);
    cudaGetSymbolAddress(&p_A,  g_A);
    cudaMemsetAsync(p_lo, 0xFF, 4);
    cudaMemsetAsync(p_hi, 0x00, 4);
    cudaMemsetAsync(p_A,  0x00, BDIM * RN * CC * sizeof(float));

    k_minmax<<<96, 256>>>(ci, ti, N * BDIM, M * BDIM);
    k_setup<<<1, 1024>>>(ls);
    k_stageA<<<dim3(N / 256, BDIM), 256, SA_FLOATS * 4>>>(ci, co);
    k_stageB<<<dim3(BDIM, RDIM / 16), 128>>>(W);
    k_stageC<<<dim3(M / 128, BDIM), 256, SC_FLOATS * 4>>>(ti, W, bias, out);
}